// round 11
// baseline (speedup 1.0000x reference)
#include <cuda_runtime.h>
#include <cuda_fp16.h>
#include <cstdint>

// Problem constants
#define Bn   64
#define Tn   2048
#define Fn   128
#define Hn   512
#define HSn  32           // hidden groups (CTAs per batch group)
#define BSn  4            // batch groups
#define BCn  16           // batches per CTA
#define NT   256          // 8 warps: 4 K-slices x 2 N-halves

// hx smem: 40 k16-groups x 136 u32 (128 used: n*8 + pos, 8 pad)
#define HXG      136
#define HX_U32   (40*HXG)              // 5440
#define GP_RS    10                    // partial row stride (even -> aligned float2)
#define GP_PER_W (64*GP_RS)            // 640
#define GP_FLOATS (8*GP_PER_W)         // 5120
#define SM_HX   0
#define SM_GP   (SM_HX + HX_U32)
#define SM_BIAS (SM_GP + GP_FLOATS)
#define SM_TOTAL (SM_BIAS + 64)        // 10624 words = 42496 B

#define FLG_STR 8

// Scratch (no cudaMalloc allowed)
__device__ float    g_hf[Bn * Hn];                 // fp32 final h (for output GEMV)
__device__ unsigned g_hx[BSn][2][HSn * 128];       // packed half2 h exchange, dbl-buffered
__device__ unsigned g_xp[BSn][Tn][8 * 128];        // pre-packed x in B-fragment layout (32MB)
__device__ unsigned g_flag[BSn * HSn * FLG_STR];

__device__ __forceinline__ unsigned h2bits(float a, float b) {
    __half2 h = __floats2half2_rn(a, b);
    return *reinterpret_cast<unsigned*>(&h);
}

__device__ __forceinline__ void mma_f16(float* c,
                                        unsigned a0, unsigned a1, unsigned a2, unsigned a3,
                                        unsigned b0, unsigned b1) {
    asm volatile(
        "mma.sync.aligned.m16n8k16.row.col.f32.f16.f16.f32 "
        "{%0,%1,%2,%3}, {%4,%5,%6,%7}, {%8,%9}, {%0,%1,%2,%3};"
        : "+f"(c[0]), "+f"(c[1]), "+f"(c[2]), "+f"(c[3])
        : "r"(a0), "r"(a1), "r"(a2), "r"(a3), "r"(b0), "r"(b1));
}

__device__ __forceinline__ float tanh_ap(float x) {
    float y;
    asm("tanh.approx.f32 %0, %1;" : "=f"(y) : "f"(x));
    return y;
}
__device__ __forceinline__ float sigmoid_ap(float x) {
    return fmaf(tanh_ap(0.5f * x), 0.5f, 0.5f);
}

__global__ void init_flags_kernel() {
    int i = blockIdx.x * blockDim.x + threadIdx.x;
    if (i < BSn * HSn * FLG_STR) g_flag[i] = 0u;
}

// Pre-pack x[b,t,f] -> g_xp[bg][t][g*128 + n*8 + pos] (half2, B-fragment layout)
__global__ void prepack_x_kernel(const float* __restrict__ x) {
    int bg = blockIdx.x >> 11;
    int t  = blockIdx.x & 2047;
    unsigned* dst = g_xp[bg][t];
    for (int j = threadIdx.x; j < 1024; j += blockDim.x) {
        int g   = j >> 7;
        int idx = j & 127;
        int n   = idx >> 3;
        int pos = idx & 7;
        int p   = (pos >> 1) | ((pos & 1) << 2);   // inverse of pos = ((p&3)<<1)|(p>>2)
        int f   = (g * 8 + p) * 2;
        const float* xb = x + ((size_t)(bg * BCn + n) * Tn + t) * Fn + f;
        float2 v = *reinterpret_cast<const float2*>(xb);
        dst[j] = h2bits(v.x, v.y);
    }
}

__global__ void __launch_bounds__(NT, 1) lstm_persist(
    const float* __restrict__ Wih,  const float* __restrict__ Whh,
    const float* __restrict__ bih,  const float* __restrict__ bhh,
    const float* __restrict__ Wout, const float* __restrict__ bout,
    float* __restrict__ out)
{
    extern __shared__ float sm[];
    unsigned* hxs = reinterpret_cast<unsigned*>(sm + SM_HX);
    float* gpart  = sm + SM_GP;
    float* bsm    = sm + SM_BIAS;

    const int tid = threadIdx.x;
    const int l   = tid & 31;
    const int w   = tid >> 5;             // warp 0..7
    const int kw  = w >> 1;               // K-slice [160kw, 160kw+160) -> groups 10kw..10kw+9
    const int nh  = w & 1;                // n-half: batches nh*8..nh*8+7
    const int q   = blockIdx.x & 31;      // hidden group (16 units)
    const int bg  = blockIdx.x >> 5;      // batch group
    const int b0  = bg * BCn;
    unsigned* flg = g_flag + bg * HSn * FLG_STR;

    // ---- one-time: A fragments (fp16) -> registers ----
    // warp: all 4 gates (M=64) x K-slice 160 = 10 k16-steps
    unsigned Ar[10][4][4];
    {
        const int r0 = l >> 2;
        const int c0 = 2 * (l & 3);
        #pragma unroll
        for (int s = 0; s < 10; ++s)
            #pragma unroll
            for (int g = 0; g < 4; ++g)
                #pragma unroll
                for (int j = 0; j < 4; ++j) {
                    int row = r0 + ((j & 1) << 3);
                    int col = c0 + ((j >> 1) << 3);
                    int grow = g * Hn + q * 16 + row;
                    int k    = kw * 160 + s * 16 + col;  // k,k+1 same side of 512
                    float v0, v1;
                    if (k < Hn) {
                        v0 = Whh[(size_t)grow * Hn + k];
                        v1 = Whh[(size_t)grow * Hn + k + 1];
                    } else {
                        v0 = Wih[(size_t)grow * Fn + (k - Hn)];
                        v1 = Wih[(size_t)grow * Fn + (k - Hn) + 1];
                    }
                    Ar[s][g][j] = h2bits(v0, v1);
                }
    }
    if (tid < 64) {
        int e = tid >> 4, r = tid & 15;
        int grow = e * Hn + q * 16 + r;
        bsm[tid] = bih[grow] + bhh[grow];
    }
    // zero hx (h0 = 0); x(0) is loaded by the copy phase at t=0
    for (int i = tid; i < HX_U32; i += NT) hxs[i] = 0u;
    __syncthreads();

    float creg = 0.f;                      // cell state: thread owns (bb, ju)
    const int bb = tid >> 4, ju = tid & 15;
    const int boffB = (nh * 8 + (l >> 2)) * 8 + 2 * (l & 3);
    const int mo = nh * 5;                 // this warp copies groups 10kw+mo .. +mo+4
    const int bar_id = 1 + kw;

    for (int t = 0; t < Tn; ++t) {
        // ---- per-pair poll of this K-slice's h producers ----
        if (t > 0) {
            const unsigned tgt = (unsigned)t;
            const int glo = 10 * kw + l;
            bool need = (l < 10) && (glo < 32) && (glo != q);
            bool ok = !need;
            for (;;) {
                if (!ok) {
                    unsigned vv;
                    asm volatile("ld.acquire.gpu.global.u32 %0, [%1];"
                                 : "=r"(vv) : "l"(flg + glo * FLG_STR) : "memory");
                    ok = vv >= tgt;
                }
                if (__all_sync(0xffffffffu, ok)) break;
                __nanosleep(26);
            }
        }
        // ---- copy this warp's 5 groups (h from g_hx, x from g_xp) ----
        {
            const unsigned* hsrc = g_hx[bg][t & 1];
            const unsigned* xsrc = g_xp[bg][t];
            #pragma unroll
            for (int i = 0; i < 5; ++i) {
                int gg = 10 * kw + mo + i;
                if (gg < 32) {
                    if (t > 0) {
                        uint4 v = __ldcg(reinterpret_cast<const uint4*>(hsrc + gg * 128) + l);
                        *reinterpret_cast<uint4*>(hxs + gg * HXG + 4 * l) = v;
                    }
                } else {
                    uint4 v = *(reinterpret_cast<const uint4*>(xsrc + (gg - 32) * 128) + l);
                    *reinterpret_cast<uint4*>(hxs + gg * HXG + 4 * l) = v;
                }
            }
        }
        asm volatile("bar.sync %0, 64;" :: "r"(bar_id) : "memory");  // pair barrier

        // ---- GEMM: warp = M64 x N8 x K160 partial (fp16) ----
        float acc[4][4];
        #pragma unroll
        for (int g = 0; g < 4; ++g)
            #pragma unroll
            for (int j = 0; j < 4; ++j) acc[g][j] = 0.f;

        #pragma unroll
        for (int s = 0; s < 10; ++s) {
            uint2 bv = *reinterpret_cast<const uint2*>(hxs + (10 * kw + s) * HXG + boffB);
            #pragma unroll
            for (int g = 0; g < 4; ++g)
                mma_f16(acc[g], Ar[s][g][0], Ar[s][g][1], Ar[s][g][2], Ar[s][g][3],
                        bv.x, bv.y);
        }

        // ---- write per-warp partials ----
        {
            int r0 = l >> 2, cc = 2 * (l & 3);
            float* gp = gpart + w * GP_PER_W;
            #pragma unroll
            for (int g = 0; g < 4; ++g) {
                *reinterpret_cast<float2*>(gp + (g * 16 + r0) * GP_RS + cc) =
                    make_float2(acc[g][0], acc[g][1]);
                *reinterpret_cast<float2*>(gp + (g * 16 + r0 + 8) * GP_RS + cc) =
                    make_float2(acc[g][2], acc[g][3]);
            }
        }
        __syncthreads();   // S1: partials ready

        // ---- reduce 4 K-partials + bias, LSTM cell ----
        {
            const int nhs = bb >> 3, cl = bb & 7;
            float gate[4];
            #pragma unroll
            for (int g = 0; g < 4; ++g) {
                int row = g * 16 + ju;
                const float* gpr = gpart + row * GP_RS + cl + nhs * GP_PER_W;
                float p0 = gpr[0 * 2 * GP_PER_W];
                float p1 = gpr[1 * 2 * GP_PER_W];
                float p2 = gpr[2 * 2 * GP_PER_W];
                float p3 = gpr[3 * 2 * GP_PER_W];
                gate[g] = bsm[row] + ((p0 + p1) + (p2 + p3));
            }
            float iv = sigmoid_ap(gate[0]);
            float fv = sigmoid_ap(gate[1]);
            float gv = tanh_ap(gate[2]);
            float ov = sigmoid_ap(gate[3]);
            creg = fv * creg + iv * gv;
            float hv = ov * tanh_ap(creg);

            float hv_hi = __shfl_down_sync(0xffffffffu, hv, 1);
            if (t + 1 < Tn) {
                if (!(ju & 1)) {
                    int jp = ju >> 1;
                    int pos = ((jp & 3) << 1) | (jp >> 2);
                    g_hx[bg][(t + 1) & 1][q * 128 + bb * 8 + pos] = h2bits(hv, hv_hi);
                }
            } else {
                g_hf[(size_t)(b0 + bb) * Hn + q * 16 + ju] = hv; // final h fp32
            }
        }
        __syncthreads();   // S2: h stores done (also protects hx overwrite next iter)
        if (tid == 0) {
            asm volatile("st.release.gpu.global.u32 [%0], %1;"
                         :: "l"(flg + q * FLG_STR), "r"((unsigned)(t + 1)) : "memory");
        }
    }

    // ---- final: out[b, o] = relu(h_T) . Wout[o] + bout[o] (layer 1 is dead code) ----
    if (q == 0) {
        if (tid < HSn) {
            for (;;) {
                unsigned vv;
                asm volatile("ld.acquire.gpu.global.u32 %0, [%1];"
                             : "=r"(vv) : "l"(flg + tid * FLG_STR) : "memory");
                if (vv >= (unsigned)Tn) break;
                __nanosleep(64);
            }
        }
        __syncthreads();
        if (tid < BCn * 4) {
            int b = tid >> 2, o = tid & 3;
            const float* hb = g_hf + (size_t)(b0 + b) * Hn;
            const float* wo = Wout + (size_t)o * Hn;
            float sum = bout[o];
            #pragma unroll 8
            for (int j = 0; j < Hn; j += 4) {
                float4 hv = __ldcg(reinterpret_cast<const float4*>(hb + j));
                float4 wv = *reinterpret_cast<const float4*>(wo + j);
                sum += fmaxf(hv.x, 0.f) * wv.x + fmaxf(hv.y, 0.f) * wv.y
                     + fmaxf(hv.z, 0.f) * wv.z + fmaxf(hv.w, 0.f) * wv.w;
            }
            out[(b0 + b) * 4 + o] = sum;
        }
    }
}

extern "C" void kernel_launch(void* const* d_in, const int* in_sizes, int n_in,
                              void* d_out, int out_size) {
    const float* x    = (const float*)d_in[0];
    const float* Wih  = (const float*)d_in[1];
    const float* Whh  = (const float*)d_in[2];
    const float* bih  = (const float*)d_in[3];
    const float* bhh  = (const float*)d_in[4];
    // d_in[5..8]: layer-1 weights — provably unused by the reference output
    const float* Wout = (const float*)d_in[9];
    const float* bout = (const float*)d_in[10];
    float* out = (float*)d_out;

    cudaFuncSetAttribute(lstm_persist, cudaFuncAttributeMaxDynamicSharedMemorySize,
                         SM_TOTAL * (int)sizeof(float));
    init_flags_kernel<<<2, 512>>>();
    prepack_x_kernel<<<BSn * Tn, 256>>>(x);
    lstm_persist<<<HSn * BSn, NT, SM_TOTAL * (int)sizeof(float)>>>(
        Wih, Whh, bih, bhh, Wout, bout, out);
}

// round 14
// speedup vs baseline: 1.6804x; 1.6804x over previous
#include <cuda_runtime.h>
#include <cuda_fp16.h>
#include <cstdint>

// Problem constants
#define Bn   64
#define Tn   2048
#define Fn   128
#define Hn   512
#define HSn  32           // hidden groups (CTAs per batch group)
#define BSn  4            // batch groups
#define BCn  16           // batches per CTA
#define NT   256          // 8 warps (R10 proven topology)

// hx smem: 40 k16-groups x 136 u32 (128 used: n*8 + pos, 8 pad)
#define HXG      136
#define HX_U32   (40*HXG)              // 5440
#define GP_RS    18                    // gpart row stride (floats, even -> aligned float2)
#define GP_PER_W (64*GP_RS)            // 1152
#define GP_FLOATS (8*GP_PER_W)         // 9216
#define SM_HX   0
#define SM_GP   (SM_HX + HX_U32)
#define SM_BIAS (SM_GP + GP_FLOATS)
#define SM_TOTAL (SM_BIAS + 64)        // 14720 words = 58880 B

#define FLG_STR 8

// Scratch (no cudaMalloc allowed)
__device__ float    g_hf[Bn * Hn];                 // fp32 final h (for output GEMV)
__device__ unsigned g_hx[BSn][2][HSn * 128];       // packed half2 h exchange, dbl-buffered
__device__ unsigned g_xp[BSn][Tn][8 * 128];        // pre-packed x in B-fragment layout (32MB)
__device__ unsigned g_flag[BSn * HSn * FLG_STR];

__device__ __forceinline__ unsigned h2bits(float a, float b) {
    __half2 h = __floats2half2_rn(a, b);
    return *reinterpret_cast<unsigned*>(&h);
}

__device__ __forceinline__ void mma_f16(float* c,
                                        unsigned a0, unsigned a1, unsigned a2, unsigned a3,
                                        unsigned b0, unsigned b1) {
    asm volatile(
        "mma.sync.aligned.m16n8k16.row.col.f32.f16.f16.f32 "
        "{%0,%1,%2,%3}, {%4,%5,%6,%7}, {%8,%9}, {%0,%1,%2,%3};"
        : "+f"(c[0]), "+f"(c[1]), "+f"(c[2]), "+f"(c[3])
        : "r"(a0), "r"(a1), "r"(a2), "r"(a3), "r"(b0), "r"(b1));
}

__device__ __forceinline__ float tanh_ap(float x) {
    float y;
    asm("tanh.approx.f32 %0, %1;" : "=f"(y) : "f"(x));
    return y;
}
__device__ __forceinline__ float sigmoid_ap(float x) {
    return fmaf(tanh_ap(0.5f * x), 0.5f, 0.5f);
}

__global__ void init_flags_kernel() {
    int i = blockIdx.x * blockDim.x + threadIdx.x;
    if (i < BSn * HSn * FLG_STR) g_flag[i] = 0u;
}

// Pre-pack x[b,t,f] -> g_xp[bg][t][g*128 + n*8 + pos] (half2, hx B-fragment layout)
__global__ void prepack_x_kernel(const float* __restrict__ x) {
    int bg = blockIdx.x >> 11;
    int t  = blockIdx.x & 2047;
    unsigned* dst = g_xp[bg][t];
    for (int j = threadIdx.x; j < 1024; j += blockDim.x) {
        int g   = j >> 7;                          // hx group 32+g
        int idx = j & 127;
        int n   = idx >> 3;
        int pos = idx & 7;
        int p   = (pos >> 1) | ((pos & 1) << 2);   // inverse of pos = ((p&3)<<1)|(p>>2)
        int f   = (g * 8 + p) * 2;
        const float* xb = x + ((size_t)(bg * BCn + n) * Tn + t) * Fn + f;
        float2 v = *reinterpret_cast<const float2*>(xb);
        dst[j] = h2bits(v.x, v.y);
    }
}

__global__ void __launch_bounds__(NT, 1) lstm_persist(
    const float* __restrict__ Wih,  const float* __restrict__ Whh,
    const float* __restrict__ bih,  const float* __restrict__ bhh,
    const float* __restrict__ Wout, const float* __restrict__ bout,
    float* __restrict__ out)
{
    extern __shared__ float sm[];
    unsigned* hxs = reinterpret_cast<unsigned*>(sm + SM_HX);
    float* gpart  = sm + SM_GP;
    float* bsm    = sm + SM_BIAS;

    const int tid = threadIdx.x;
    const int l   = tid & 31;
    const int w   = tid >> 5;             // warp 0..7 => GEMM k-slice groups 5w..5w+4
    const int q   = blockIdx.x & 31;      // hidden group (16 units)
    const int bg  = blockIdx.x >> 5;      // batch group
    const int b0  = bg * BCn;
    unsigned* flg = g_flag + bg * HSn * FLG_STR;

    // ---- one-time: A fragments (fp16) -> registers ----
    // warp w: all 4 gates (M=64) x K-slice 80 = 5 k16-steps; 4 b32 regs per (s,g)
    unsigned Ar[5][4][4];
    {
        const int r0 = l >> 2;
        const int c0 = 2 * (l & 3);
        #pragma unroll
        for (int s = 0; s < 5; ++s)
            #pragma unroll
            for (int g = 0; g < 4; ++g)
                #pragma unroll
                for (int j = 0; j < 4; ++j) {
                    int row = r0 + ((j & 1) << 3);
                    int col = c0 + ((j >> 1) << 3);
                    int grow = g * Hn + q * 16 + row;
                    int k    = w * 80 + s * 16 + col;    // k,k+1 same side of 512
                    float v0, v1;
                    if (k < Hn) {
                        v0 = Whh[(size_t)grow * Hn + k];
                        v1 = Whh[(size_t)grow * Hn + k + 1];
                    } else {
                        v0 = Wih[(size_t)grow * Fn + (k - Hn)];
                        v1 = Wih[(size_t)grow * Fn + (k - Hn) + 1];
                    }
                    Ar[s][g][j] = h2bits(v0, v1);
                }
    }
    if (tid < 64) {
        int e = tid >> 4, r = tid & 15;
        int grow = e * Hn + q * 16 + r;
        bsm[tid] = bih[grow] + bhh[grow];
    }
    // zero hx (h0 = 0), then copy x(0) from prepacked g_xp (warp w -> group 32+w)
    for (int i = tid; i < HX_U32; i += NT) hxs[i] = 0u;
    __syncthreads();
    {
        const unsigned* xsrc = g_xp[bg][0];
        uint4 v = __ldcg(reinterpret_cast<const uint4*>(xsrc + w * 128) + l);
        *reinterpret_cast<uint4*>(hxs + (32 + w) * HXG + 4 * l) = v;
    }

    float creg = 0.f;                      // cell state: thread owns (bb, ju)
    const int bb = tid >> 4, ju = tid & 15;
    const int n0_   = l >> 2;
    const int boff0 = n0_ * 8 + 2 * (l & 3);
    const int boff1 = (n0_ + 8) * 8 + 2 * (l & 3);

    for (int t = 0; t < Tn; ++t) {
        __syncthreads();   // hx(t) ready

        // ---- GEMM: warp computes 64x16 partial over its K=80 slice (fp16) ----
        float acc[4][2][4];
        #pragma unroll
        for (int g = 0; g < 4; ++g)
            #pragma unroll
            for (int h2 = 0; h2 < 2; ++h2)
                #pragma unroll
                for (int j = 0; j < 4; ++j) acc[g][h2][j] = 0.f;

        #pragma unroll
        for (int s = 0; s < 5; ++s) {
            const unsigned* gb = hxs + (5 * w + s) * HXG;
            uint2 v0 = *reinterpret_cast<const uint2*>(gb + boff0);
            uint2 v1 = *reinterpret_cast<const uint2*>(gb + boff1);
            #pragma unroll
            for (int g = 0; g < 4; ++g) {
                mma_f16(acc[g][0], Ar[s][g][0], Ar[s][g][1], Ar[s][g][2], Ar[s][g][3], v0.x, v0.y);
                mma_f16(acc[g][1], Ar[s][g][0], Ar[s][g][1], Ar[s][g][2], Ar[s][g][3], v1.x, v1.y);
            }
        }

        // ---- write per-warp partials ----
        {
            int r0 = l >> 2, cc0 = 2 * (l & 3);
            float* gp = gpart + w * GP_PER_W;
            #pragma unroll
            for (int g = 0; g < 4; ++g)
                #pragma unroll
                for (int h2 = 0; h2 < 2; ++h2) {
                    *reinterpret_cast<float2*>(gp + (g * 16 + r0) * GP_RS + h2 * 8 + cc0) =
                        make_float2(acc[g][h2][0], acc[g][h2][1]);
                    *reinterpret_cast<float2*>(gp + (g * 16 + r0 + 8) * GP_RS + h2 * 8 + cc0) =
                        make_float2(acc[g][h2][2], acc[g][h2][3]);
                }
        }
        __syncthreads();   // S1: partials ready

        // ---- reduce 8 partials (tree) + bias, LSTM cell ----
        float gate[4];
        #pragma unroll
        for (int g = 0; g < 4; ++g) {
            int row = g * 16 + ju;
            const float* gpr = gpart + row * GP_RS + bb;
            float p0 = gpr[0 * GP_PER_W];
            float p1 = gpr[1 * GP_PER_W];
            float p2 = gpr[2 * GP_PER_W];
            float p3 = gpr[3 * GP_PER_W];
            float p4 = gpr[4 * GP_PER_W];
            float p5 = gpr[5 * GP_PER_W];
            float p6 = gpr[6 * GP_PER_W];
            float p7 = gpr[7 * GP_PER_W];
            gate[g] = bsm[row] + (((p0 + p1) + (p2 + p3)) + ((p4 + p5) + (p6 + p7)));
        }
        float iv = sigmoid_ap(gate[0]);
        float fv = sigmoid_ap(gate[1]);
        float gv = tanh_ap(gate[2]);
        float ov = sigmoid_ap(gate[3]);
        creg = fv * creg + iv * gv;
        float hv = ov * tanh_ap(creg);

        // ---- pack h pair (ju even lanes) -> local smem (own group) + gmem exchange ----
        float hv_hi = __shfl_down_sync(0xffffffffu, hv, 1);
        if (t + 1 < Tn) {
            if (!(ju & 1)) {
                int jp = ju >> 1;
                int pos = ((jp & 3) << 1) | (jp >> 2);
                unsigned pk = h2bits(hv, hv_hi);
                hxs[q * HXG + bb * 8 + pos] = pk;            // own group local (no gmem trip)
                g_hx[bg][(t + 1) & 1][q * 128 + bb * 8 + pos] = pk;
            }
        } else {
            g_hf[(size_t)(b0 + bb) * Hn + q * 16 + ju] = hv; // final h fp32
        }
        __syncthreads();   // S2: h stores done
        if (tid == 0) {
            asm volatile("st.release.gpu.global.u32 [%0], %1;"
                         :: "l"(flg + q * FLG_STR), "r"((unsigned)(t + 1)) : "memory");
        }

        if (t + 1 < Tn) {
            // ---- per-warp poll: warp w needs producers 4w..4w+3 ----
            const unsigned tgt = (unsigned)(t + 1);
            const int qq = 4 * w + (l & 3);
            bool need = (l < 4) && (qq != q);
            bool ok = !need;
            for (;;) {
                if (!ok) {
                    unsigned vv;
                    asm volatile("ld.acquire.gpu.global.u32 %0, [%1];"
                                 : "=r"(vv) : "l"(flg + qq * FLG_STR) : "memory");
                    ok = vv >= tgt;
                }
                if (__all_sync(0xffffffffu, ok)) break;
                __nanosleep(26);
            }
            // ---- copy this warp's 4 h groups + 1 x group (packed u32, uint4) ----
            const unsigned* src = g_hx[bg][(t + 1) & 1];
            #pragma unroll
            for (int s = 0; s < 4; ++s) {
                int gg = 4 * w + s;
                if (gg == q) continue;
                uint4 v = __ldcg(reinterpret_cast<const uint4*>(src + gg * 128) + l);
                *reinterpret_cast<uint4*>(hxs + gg * HXG + 4 * l) = v;
            }
            {
                const unsigned* xsrc = g_xp[bg][t + 1];
                uint4 v = __ldcg(reinterpret_cast<const uint4*>(xsrc + w * 128) + l);
                *reinterpret_cast<uint4*>(hxs + (32 + w) * HXG + 4 * l) = v;
            }
        }
    }

    // ---- final: out[b, o] = relu(h_T) . Wout[o] + bout[o] (layer 1 is dead code) ----
    if (q == 0) {
        if (tid < HSn) {
            for (;;) {
                unsigned vv;
                asm volatile("ld.acquire.gpu.global.u32 %0, [%1];"
                             : "=r"(vv) : "l"(flg + tid * FLG_STR) : "memory");
                if (vv >= (unsigned)Tn) break;
                __nanosleep(64);
            }
        }
        __syncthreads();
        if (tid < BCn * 4) {
            int b = tid >> 2, o = tid & 3;
            const float* hb = g_hf + (size_t)(b0 + b) * Hn;
            const float* wo = Wout + (size_t)o * Hn;
            float sum = bout[o];
            #pragma unroll 8
            for (int j = 0; j < Hn; j += 4) {
                float4 hv = __ldcg(reinterpret_cast<const float4*>(hb + j));
                float4 wv = *reinterpret_cast<const float4*>(wo + j);
                sum += fmaxf(hv.x, 0.f) * wv.x + fmaxf(hv.y, 0.f) * wv.y
                     + fmaxf(hv.z, 0.f) * wv.z + fmaxf(hv.w, 0.f) * wv.w;
            }
            out[(b0 + b) * 4 + o] = sum;
        }
    }
}

extern "C" void kernel_launch(void* const* d_in, const int* in_sizes, int n_in,
                              void* d_out, int out_size) {
    const float* x    = (const float*)d_in[0];
    const float* Wih  = (const float*)d_in[1];
    const float* Whh  = (const float*)d_in[2];
    const float* bih  = (const float*)d_in[3];
    const float* bhh  = (const float*)d_in[4];
    // d_in[5..8]: layer-1 weights — provably unused by the reference output
    const float* Wout = (const float*)d_in[9];
    const float* bout = (const float*)d_in[10];
    float* out = (float*)d_out;

    cudaFuncSetAttribute(lstm_persist, cudaFuncAttributeMaxDynamicSharedMemorySize,
                         SM_TOTAL * (int)sizeof(float));
    init_flags_kernel<<<2, 512>>>();
    prepack_x_kernel<<<BSn * Tn, 256>>>(x);
    lstm_persist<<<HSn * BSn, NT, SM_TOTAL * (int)sizeof(float)>>>(
        Wih, Whh, bih, bhh, Wout, bout, out);
}